// round 3
// baseline (speedup 1.0000x reference)
#include <cuda_runtime.h>

// Problem constants
#define BATCH  32768
#define DD     16     // (lmax+1)^2
#define RR     64     // RANK
#define CO     64     // CH_OUT (== CH_IN1)
#define CI2    32     // CH_IN2

// out[b,c,o] = sum_r C[c,r] * t1[b,r,o] * t3[b,r,o]
//   t1[b,r,o] = sum_i x1[b,i,o] * A[i,r]
//   t2[b,r,v] = sum_j x2[b,j,v] * B[j,r]
//   t3[b,r,o] = sum_v t2[b,r,v] * w[b,o,v]
//
// One CTA per batch element. 256 threads = 8 warps.
// lane (tid&31) -> o-pair (o = 2*lane, 2*lane+1); warp (tid>>5) -> r-group of 8.
// All r-indexed smem operands are warp-uniform float4 broadcasts; all o-indexed
// operands are lane-contiguous float2 -> conflict-free crossbar traffic.

__global__ __launch_bounds__(256, 2)
void cp_tp_kernel(const float* __restrict__ x1,
                  const float* __restrict__ x2,
                  const float* __restrict__ w,
                  const float* __restrict__ A,
                  const float* __restrict__ Bm,
                  const float* __restrict__ Cm,
                  float* __restrict__ out)
{
    const int b   = blockIdx.x;
    const int tid = threadIdx.x;

    __shared__ union {
        struct {
            float x1s[DD * CO];     // 1024  [i][o]
            float x2s[DD * CI2];    // 512   [i][v]
            float wT [CI2 * 66];    // 2112  [v][o]  stride 66 (8B-aligned, bank-spread)
            float t2T[CI2 * 68];    // 2176  [v][r]  stride 68 (16B-aligned)
            float As [DD * RR];     // 1024  [i][r]
            float Bs [DD * RR];     // 1024  [i][r]
            float CsT[RR * 20];     // 1280  [r][c]  stride 20 (16B-aligned)
        } s;
        float red[8 * DD * CO];     // 8192 floats = 32 KB partial-sum buffer (aliased)
    } sm;

    // ---------------- fill shared memory ----------------
    {
        // x1: 1024 floats = 256 float4, one per thread (coalesced)
        ((float4*)sm.s.x1s)[tid] = ((const float4*)(x1 + (size_t)b * DD * CO))[tid];
        // x2: 512 floats = 128 float4
        if (tid < 128)
            ((float4*)sm.s.x2s)[tid] = ((const float4*)(x2 + (size_t)b * DD * CI2))[tid];
        // A, B: 1024 floats each
        ((float4*)sm.s.As)[tid] = ((const float4*)A)[tid];
        ((float4*)sm.s.Bs)[tid] = ((const float4*)Bm)[tid];
        // C transpose into CsT[r][c]
        #pragma unroll
        for (int k = 0; k < 4; k++) {
            int idx = tid + k * 256;
            int c = idx >> 6, r = idx & 63;
            sm.s.CsT[r * 20 + c] = Cm[idx];
        }
        // w[b][o][v] transpose into wT[v][o]
        const float* wg = w + (size_t)b * CO * CI2;
        #pragma unroll
        for (int k = 0; k < 8; k++) {
            int idx = tid + k * 256;
            int o = idx >> 5, v = idx & 31;
            sm.s.wT[v * 66 + o] = wg[idx];
        }
    }
    __syncthreads();

    const int lane = tid & 31;
    const int g    = tid >> 5;     // warp id = r-group
    const int r0   = g * 8;
    const int oo   = lane * 2;

    // ---------------- t2 phase: t2T[v][r0..r0+7], v = lane ----------------
    {
        float acc[8];
        #pragma unroll
        for (int k = 0; k < 8; k++) acc[k] = 0.f;
        const int v = lane;
        #pragma unroll
        for (int i = 0; i < DD; i++) {
            float  xv = sm.s.x2s[i * CI2 + v];                       // lane-contiguous
            float4 b0 = *(const float4*)&sm.s.Bs[i * RR + r0];       // warp-uniform
            float4 b1 = *(const float4*)&sm.s.Bs[i * RR + r0 + 4];
            acc[0] += xv * b0.x; acc[1] += xv * b0.y;
            acc[2] += xv * b0.z; acc[3] += xv * b0.w;
            acc[4] += xv * b1.x; acc[5] += xv * b1.y;
            acc[6] += xv * b1.z; acc[7] += xv * b1.w;
        }
        *(float4*)&sm.s.t2T[v * 68 + r0]     = make_float4(acc[0], acc[1], acc[2], acc[3]);
        *(float4*)&sm.s.t2T[v * 68 + r0 + 4] = make_float4(acc[4], acc[5], acc[6], acc[7]);
    }
    __syncthreads();

    // ---------------- main: t1 and t3 for (8 r) x (2 o) ----------------
    float t1a[8][2], t3a[8][2];
    #pragma unroll
    for (int k = 0; k < 8; k++) {
        t1a[k][0] = t1a[k][1] = 0.f;
        t3a[k][0] = t3a[k][1] = 0.f;
    }

    #pragma unroll
    for (int i = 0; i < DD; i++) {
        float2 xv = *(const float2*)&sm.s.x1s[i * CO + oo];          // lane-contiguous
        float4 a0 = *(const float4*)&sm.s.As[i * RR + r0];           // warp-uniform
        float4 a1 = *(const float4*)&sm.s.As[i * RR + r0 + 4];
        float av[8] = {a0.x, a0.y, a0.z, a0.w, a1.x, a1.y, a1.z, a1.w};
        #pragma unroll
        for (int k = 0; k < 8; k++) {
            t1a[k][0] += av[k] * xv.x;
            t1a[k][1] += av[k] * xv.y;
        }
    }

    #pragma unroll
    for (int v = 0; v < CI2; v++) {
        float2 wv = *(const float2*)&sm.s.wT[v * 66 + oo];           // lane-contiguous
        float4 t0 = *(const float4*)&sm.s.t2T[v * 68 + r0];          // warp-uniform
        float4 t1v = *(const float4*)&sm.s.t2T[v * 68 + r0 + 4];
        float tv[8] = {t0.x, t0.y, t0.z, t0.w, t1v.x, t1v.y, t1v.z, t1v.w};
        #pragma unroll
        for (int k = 0; k < 8; k++) {
            t3a[k][0] += tv[k] * wv.x;
            t3a[k][1] += tv[k] * wv.y;
        }
    }

    // ---------------- fold C: partial out[c][oo..oo+1] over this warp's 8 r ----------------
    float oacc[DD][2];
    #pragma unroll
    for (int c = 0; c < DD; c++) oacc[c][0] = oacc[c][1] = 0.f;

    #pragma unroll
    for (int k = 0; k < 8; k++) {
        float p0 = t1a[k][0] * t3a[k][0];
        float p1 = t1a[k][1] * t3a[k][1];
        int r = r0 + k;
        float4 c0 = *(const float4*)&sm.s.CsT[r * 20 + 0];           // warp-uniform
        float4 c1 = *(const float4*)&sm.s.CsT[r * 20 + 4];
        float4 c2 = *(const float4*)&sm.s.CsT[r * 20 + 8];
        float4 c3 = *(const float4*)&sm.s.CsT[r * 20 + 12];
        float cv[16] = {c0.x, c0.y, c0.z, c0.w, c1.x, c1.y, c1.z, c1.w,
                        c2.x, c2.y, c2.z, c2.w, c3.x, c3.y, c3.z, c3.w};
        #pragma unroll
        for (int c = 0; c < DD; c++) {
            oacc[c][0] += cv[c] * p0;
            oacc[c][1] += cv[c] * p1;
        }
    }

    // ---------------- cross-warp reduction over 8 r-groups ----------------
    __syncthreads();   // everyone done reading scratch before aliasing red over it
    #pragma unroll
    for (int c = 0; c < DD; c++)
        *(float2*)&sm.red[g * (DD * CO) + c * CO + oo] = make_float2(oacc[c][0], oacc[c][1]);
    __syncthreads();

    {
        int c  = tid >> 4;
        int o0 = (tid & 15) * 4;
        float4 s = *(const float4*)&sm.red[c * CO + o0];
        #pragma unroll
        for (int gg = 1; gg < 8; gg++) {
            float4 t = *(const float4*)&sm.red[gg * (DD * CO) + c * CO + o0];
            s.x += t.x; s.y += t.y; s.z += t.z; s.w += t.w;
        }
        *(float4*)(out + (size_t)b * DD * CO + c * CO + o0) = s;
    }
}

extern "C" void kernel_launch(void* const* d_in, const int* in_sizes, int n_in,
                              void* d_out, int out_size)
{
    const float* x1 = (const float*)d_in[0];  // (32768, 16, 64)
    const float* x2 = (const float*)d_in[1];  // (32768, 16, 32)
    const float* w  = (const float*)d_in[2];  // (32768, 64, 32)
    const float* A  = (const float*)d_in[3];  // (16, 64)
    const float* B  = (const float*)d_in[4];  // (16, 64)
    const float* C  = (const float*)d_in[5];  // (16, 64)
    float* out = (float*)d_out;               // (32768, 16, 64)

    cp_tp_kernel<<<BATCH, 256>>>(x1, x2, w, A, B, C, out);
}